// round 4
// baseline (speedup 1.0000x reference)
#include <cuda_runtime.h>
#include <cstdint>

// imgs (B,L,M,C,H,W) f32, ts2img_weights (B,L,M) f32
// out (B,L,K,H,W) f32: out[b,l,k] = s * imgs[b,l,topk_idx(k),0]
// s = (1 - w_sel) + w_sel. Non-selected straight-through terms are exactly 0.

#define B_ 32
#define L_ 7
#define M_ 6
#define C_ 3
#define H_ 128
#define W_ 128
#define K_ 3
#define HW_ (H_ * W_)                       // 16384 floats per slice
#define NSLICE_ (B_ * L_ * K_)              // 672
#define CHUNK_ 8192                         // floats per block
#define CHUNKS_PER_SLICE_ (HW_ / CHUNK_)    // 2
#define THREADS_ 256
#define VEC_ITERS_ (CHUNK_ / 4 / THREADS_)  // 8 float4 per thread

struct Desc { int off; float s; };          // src float-offset into imgs, scale
__device__ Desc g_desc[NSLICE_];

// ---- Stage 1: per-(b,l,k) top-k selection -> descriptor -------------------
__global__ void mt2v_desc_kernel(const float* __restrict__ wts)
{
    int idx = blockIdx.x * blockDim.x + threadIdx.x;   // 0 .. NSLICE_-1
    if (idx >= NSLICE_) return;
    int k  = idx % K_;
    int bl = idx / K_;

    float wv[M_];
#pragma unroll
    for (int m = 0; m < M_; m++) wv[m] = __ldg(&wts[bl * M_ + m]);

    // Stable top-k (strict > => lowest index wins ties, matching lax.top_k).
    int sel = 0;
    bool used[M_];
#pragma unroll
    for (int m = 0; m < M_; m++) used[m] = false;
#pragma unroll
    for (int kk = 0; kk < K_; kk++) {
        float best = -3.402823466e+38f;
        int bi = 0;
#pragma unroll
        for (int m = 0; m < M_; m++)
            if (!used[m] && wv[m] > best) { best = wv[m]; bi = m; }
        used[bi] = true;
        if (kk == k) sel = bi;
    }

    Desc d;
    d.off = (bl * M_ + sel) * (C_ * HW_);   // channel 0 of imgs[b,l,sel]
    d.s   = (1.0f - wv[sel]) + wv[sel];
    g_desc[idx] = d;
}

// ---- Stage 2: scaled slice copy, HARD-forced 8-deep LDG.128 batching ------
// Both loads AND stores are volatile asm: volatile asms are strictly ordered
// among themselves, so all 8 LDG.128 issue before the first STG.128.
__global__ __launch_bounds__(THREADS_) void mt2v_gather_kernel(
    const float* __restrict__ imgs,
    float* __restrict__ out)
{
    const int blk   = blockIdx.x;
    const int chunk = blk % CHUNKS_PER_SLICE_;
    const int slice = blk / CHUNKS_PER_SLICE_;

    const Desc d = g_desc[slice];           // single 8B load, L2-hot
    const float s = d.s;

    const float4* __restrict__ src =
        reinterpret_cast<const float4*>(imgs + (size_t)d.off)
        + (size_t)chunk * (CHUNK_ / 4) + threadIdx.x;
    float4* __restrict__ dst =
        reinterpret_cast<float4*>(out) + (size_t)slice * (HW_ / 4)
        + (size_t)chunk * (CHUNK_ / 4) + threadIdx.x;

    float4 v[VEC_ITERS_];
#pragma unroll
    for (int i = 0; i < VEC_ITERS_; i++) {
        asm volatile("ld.global.nc.v4.f32 {%0,%1,%2,%3}, [%4];"
                     : "=f"(v[i].x), "=f"(v[i].y), "=f"(v[i].z), "=f"(v[i].w)
                     : "l"(src + i * THREADS_));
    }

#pragma unroll
    for (int i = 0; i < VEC_ITERS_; i++) {
        float x = v[i].x * s, y = v[i].y * s, z = v[i].z * s, w = v[i].w * s;
        asm volatile("st.global.v4.f32 [%0], {%1,%2,%3,%4};"
                     :: "l"(dst + i * THREADS_),
                        "f"(x), "f"(y), "f"(z), "f"(w)
                     : "memory");
    }
}

extern "C" void kernel_launch(void* const* d_in, const int* in_sizes, int n_in,
                              void* d_out, int out_size)
{
    const float* imgs = (const float*)d_in[0];
    const float* wts  = (const float*)d_in[1];
    float* out        = (float*)d_out;

    mt2v_desc_kernel<<<(NSLICE_ + 223) / 224, 224>>>(wts);
    mt2v_gather_kernel<<<NSLICE_ * CHUNKS_PER_SLICE_, THREADS_>>>(imgs, out);
}

// round 5
// speedup vs baseline: 1.0194x; 1.0194x over previous
#include <cuda_runtime.h>
#include <cstdint>

// imgs (B,L,M,C,H,W) f32, ts2img_weights (B,L,M) f32
// out (B,L,K,H,W) f32: out[b,l,k] = s * imgs[b,l,topk_idx(k),0]
// s = (1 - w_sel) + w_sel. Non-selected straight-through terms are exactly 0.

#define B_ 32
#define L_ 7
#define M_ 6
#define C_ 3
#define H_ 128
#define W_ 128
#define K_ 3
#define HW_ (H_ * W_)                       // 16384 floats per slice
#define NSLICE_ (B_ * L_ * K_)              // 672
#define CHUNK_ 8192                         // floats per block
#define CHUNK_BYTES_ (CHUNK_ * 4)           // 32768 B
#define CHUNKS_PER_SLICE_ (HW_ / CHUNK_)    // 2
#define THREADS_ 256
#define VEC_ITERS_ (CHUNK_ / 4 / THREADS_)  // 8 float4 per thread

struct Desc { int off; float s; };          // src float-offset into imgs, scale
__device__ Desc g_desc[NSLICE_];

// ---- Stage 1: per-(b,l,k) top-k selection -> descriptor -------------------
__global__ void mt2v_desc_kernel(const float* __restrict__ wts)
{
    int idx = blockIdx.x * blockDim.x + threadIdx.x;   // 0 .. NSLICE_-1
    if (idx >= NSLICE_) return;
    int k  = idx % K_;
    int bl = idx / K_;

    float wv[M_];
#pragma unroll
    for (int m = 0; m < M_; m++) wv[m] = __ldg(&wts[bl * M_ + m]);

    // Stable top-k (strict > => lowest index wins ties, matching lax.top_k).
    int sel = 0;
    bool used[M_];
#pragma unroll
    for (int m = 0; m < M_; m++) used[m] = false;
#pragma unroll
    for (int kk = 0; kk < K_; kk++) {
        float best = -3.402823466e+38f;
        int bi = 0;
#pragma unroll
        for (int m = 0; m < M_; m++)
            if (!used[m] && wv[m] > best) { best = wv[m]; bi = m; }
        used[bi] = true;
        if (kk == k) sel = bi;
    }

    Desc d;
    d.off = (bl * M_ + sel) * (C_ * HW_);   // channel 0 of imgs[b,l,sel]
    d.s   = (1.0f - wv[sel]) + wv[sel];
    g_desc[idx] = d;
}

__device__ __forceinline__ uint32_t smem_u32(const void* p) {
    uint32_t a;
    asm("{ .reg .u64 t; cvta.to.shared.u64 t, %1; cvt.u32.u64 %0, t; }"
        : "=r"(a) : "l"(p));
    return a;
}

// ---- Stage 2: TMA bulk G->S copy, then LDS/scale/STG ----------------------
// cp.async.bulk has no destination register, so the full 32KB transfer is
// hardware-pipelined regardless of ptxas scheduling heuristics.
__global__ __launch_bounds__(THREADS_) void mt2v_gather_kernel(
    const float* __restrict__ imgs,
    float* __restrict__ out)
{
    __shared__ alignas(128) float buf[CHUNK_];
    __shared__ alignas(8) unsigned long long mbar;

    const int blk   = blockIdx.x;
    const int chunk = blk % CHUNKS_PER_SLICE_;
    const int slice = blk / CHUNKS_PER_SLICE_;

    const Desc d = g_desc[slice];           // 8B load, L2-hot; gives s to all
    const uint32_t mbar_a = smem_u32(&mbar);
    const uint32_t buf_a  = smem_u32(buf);

    if (threadIdx.x == 0) {
        asm volatile("mbarrier.init.shared.b64 [%0], 1;" :: "r"(mbar_a) : "memory");
    }
    __syncthreads();

    if (threadIdx.x == 0) {
        const float* src = imgs + (size_t)d.off + (size_t)chunk * CHUNK_;
        asm volatile("mbarrier.arrive.expect_tx.shared.b64 _, [%0], %1;"
                     :: "r"(mbar_a), "r"((uint32_t)CHUNK_BYTES_) : "memory");
        asm volatile("cp.async.bulk.shared::cta.global.mbarrier::complete_tx::bytes "
                     "[%0], [%1], %2, [%3];"
                     :: "r"(buf_a), "l"(src), "r"((uint32_t)CHUNK_BYTES_), "r"(mbar_a)
                     : "memory");
    }

    // Wait for the bulk copy (phase parity 0; barrier used once per block).
    {
        uint32_t done;
        asm volatile(
            "{\n\t"
            ".reg .pred p;\n\t"
            "mbarrier.try_wait.parity.acquire.cta.shared::cta.b64 p, [%1], 0;\n\t"
            "selp.b32 %0, 1, 0, p;\n\t"
            "}" : "=r"(done) : "r"(mbar_a) : "memory");
        if (!done) {
            asm volatile(
                "{\n\t"
                ".reg .pred P1;\n\t"
                "W_%=:\n\t"
                "mbarrier.try_wait.parity.acquire.cta.shared::cta.b64 P1, [%0], 0, 0x989680;\n\t"
                "@P1 bra.uni D_%=;\n\t"
                "bra.uni W_%=;\n\t"
                "D_%=:\n\t"
                "}" :: "r"(mbar_a) : "memory");
        }
    }

    const float s = d.s;
    const float4* __restrict__ sb = reinterpret_cast<const float4*>(buf);
    float4* __restrict__ dst =
        reinterpret_cast<float4*>(out) + (size_t)slice * (HW_ / 4)
        + (size_t)chunk * (CHUNK_ / 4) + threadIdx.x;

#pragma unroll
    for (int i = 0; i < VEC_ITERS_; i++) {
        float4 v = sb[threadIdx.x + i * THREADS_];
        v.x *= s; v.y *= s; v.z *= s; v.w *= s;
        dst[i * THREADS_] = v;
    }
}

extern "C" void kernel_launch(void* const* d_in, const int* in_sizes, int n_in,
                              void* d_out, int out_size)
{
    const float* imgs = (const float*)d_in[0];
    const float* wts  = (const float*)d_in[1];
    float* out        = (float*)d_out;

    mt2v_desc_kernel<<<(NSLICE_ + 223) / 224, 224>>>(wts);
    mt2v_gather_kernel<<<NSLICE_ * CHUNKS_PER_SLICE_, THREADS_>>>(imgs, out);
}